// round 14
// baseline (speedup 1.0000x reference)
#include <cuda_runtime.h>
#include <cstdint>

#define NV      8192
#define FEAT    256
#define HIDD    64
#define ALPHA_S 0.2f
#define JSPLIT  8
#define JCHUNK  (NV / JSPLIT)     // 1024
#define JTILE   64
#define M_TILE  128

// ---------------- device scratch (no allocation allowed) ----------------
__device__ float g_h[NV * HIDD];
__device__ float g_ssrc[NV];
__device__ float g_sdst[NV];
__device__ float g_acc[JSPLIT][NV * HIDD];
__device__ float g_l[JSPLIT][NV];

// ---------------- helpers ----------------
__device__ __forceinline__ uint32_t tf32_rna(float x) {
    uint32_t r;
    asm("cvt.rna.tf32.f32 %0, %1;" : "=r"(r) : "f"(x));
    return r;
}

// m16n8k8 tf32 HMMA (baseline PTX, sm_80+)
__device__ __forceinline__ void mma_tf32(float* d, const uint32_t* a,
                                         uint32_t b0, uint32_t b1) {
    asm volatile(
        "mma.sync.aligned.m16n8k8.row.col.f32.tf32.tf32.f32 "
        "{%0,%1,%2,%3}, {%4,%5,%6,%7}, {%8,%9}, {%0,%1,%2,%3};"
        : "+f"(d[0]), "+f"(d[1]), "+f"(d[2]), "+f"(d[3])
        : "r"(a[0]), "r"(a[1]), "r"(a[2]), "r"(a[3]), "r"(b0), "r"(b1));
}

// ---------------- Kernel 1: h = X @ W, fused s_src/s_dst ----------------
__global__ __launch_bounds__(256) void k_gemm_h(const float* __restrict__ X,
                                                const float* __restrict__ W,
                                                const float* __restrict__ a) {
    __shared__ __align__(16) float Xs[64 * 68];
    __shared__ __align__(16) float Ws[64 * 64];
    const int t  = threadIdx.x;
    const int rb = blockIdx.x * 64;
    const int r  = t >> 2;
    const int q  = t & 3;

    float acc[16];
#pragma unroll
    for (int i = 0; i < 16; i++) acc[i] = 0.f;

    for (int kc = 0; kc < FEAT; kc += 64) {
#pragma unroll
        for (int k = 0; k < 4; k++) {
            int p = t + 256 * k, row = p >> 4, c4 = p & 15;
            *(float4*)&Xs[row * 68 + c4 * 4] =
                *(const float4*)&X[(size_t)(rb + row) * FEAT + kc + c4 * 4];
        }
#pragma unroll
        for (int k = 0; k < 4; k++) {
            int p = t + 256 * k, row = p >> 4, c4 = p & 15;
            *(float4*)&Ws[row * 64 + c4 * 4] =
                *(const float4*)&W[(size_t)(kc + row) * HIDD + c4 * 4];
        }
        __syncthreads();
#pragma unroll 16
        for (int k = 0; k < 64; k++) {
            float x = Xs[r * 68 + k];
#pragma unroll
            for (int g = 0; g < 4; g++) {
                float4 wv = *(const float4*)&Ws[k * 64 + q * 16 + g * 4];
                acc[g * 4 + 0] = fmaf(x, wv.x, acc[g * 4 + 0]);
                acc[g * 4 + 1] = fmaf(x, wv.y, acc[g * 4 + 1]);
                acc[g * 4 + 2] = fmaf(x, wv.z, acc[g * 4 + 2]);
                acc[g * 4 + 3] = fmaf(x, wv.w, acc[g * 4 + 3]);
            }
        }
        __syncthreads();
    }
#pragma unroll
    for (int g = 0; g < 4; g++)
        *(float4*)&g_h[(size_t)(rb + r) * HIDD + q * 16 + g * 4] =
            make_float4(acc[g * 4], acc[g * 4 + 1], acc[g * 4 + 2], acc[g * 4 + 3]);

    // fused s_src/s_dst: per-thread 16-dim partial dot, reduce over q-group
    float ps = 0.f, pd = 0.f;
#pragma unroll
    for (int k = 0; k < 16; k++) {
        ps = fmaf(acc[k], __ldg(&a[q * 16 + k]), ps);
        pd = fmaf(acc[k], __ldg(&a[64 + q * 16 + k]), pd);
    }
    ps += __shfl_xor_sync(0xffffffffu, ps, 1);
    ps += __shfl_xor_sync(0xffffffffu, ps, 2);
    pd += __shfl_xor_sync(0xffffffffu, pd, 1);
    pd += __shfl_xor_sync(0xffffffffu, pd, 2);
    if (q == 0) { g_ssrc[rb + r] = ps; g_sdst[rb + r] = pd; }
}

// ---------------- Kernel 2: fused w-phase + tf32 mma.sync aggregation ----------------
// 256 threads / 8 warps. M_TILE=128 i-rows, JTILE=64 j per tile.
// Warp w owns i rows [w*16, w*16+16) x all 64 dims (mb=1, nb=8, kc=8).
// Conflict-free strides: w_s 68 (A banks 4g+c), h_s 72 (B banks 8c+g).
#define WS_STRIDE 68
#define HS_STRIDE 72
#define SMEM_WS_WORDS (M_TILE * WS_STRIDE)          // 8704
#define SMEM_DYN ((SMEM_WS_WORDS + JTILE * HS_STRIDE) * 4)  // 53248 B

__global__ __launch_bounds__(256, 3) void k_main(const int* __restrict__ adj) {
    extern __shared__ __align__(16) uint32_t sm[];
    uint32_t* w_s = sm;                      // [128][68]
    uint32_t* h_s = sm + SMEM_WS_WORDS;      // [64][72]

    const int t = threadIdx.x, lane = t & 31, warp = t >> 5;
    const int g = lane >> 2, c = lane & 3;
    const int rb = blockIdx.x * M_TILE;
    const int split = blockIdx.y;
    const int j0 = split * JCHUNK;

    // w-phase mapping: one i-row per thread-pair, jh = 32-j half
    const int i  = t >> 1;
    const int jh = t & 1;
    const float ssrc = g_ssrc[rb + i];
    const int* arow = adj + (size_t)(rb + i) * NV + j0 + jh * 32;
    float lp = 0.f;

    // h staging mapping
    const int hr = t >> 2;     // 0..63 (j row)
    const int hq = t & 3;      // 16-dim quarter

    float C[8][4];
#pragma unroll
    for (int nb = 0; nb < 8; nb++)
#pragma unroll
        for (int k = 0; k < 4; k++) C[nb][k] = 0.f;

    for (int it = 0; it < JCHUNK / JTILE; ++it) {
        const int jb = j0 + it * JTILE;

        // ---- issue all adj loads up front (MLP=8, 128B contiguous/thread) ----
        int4 av[8];
        const int* ap = arow + it * JTILE;
#pragma unroll
        for (int q = 0; q < 8; q++) av[q] = *(const int4*)(ap + q * 4);

        // ---- stage h tile [64 j][64 d] as tf32 ----
        {
            const float* hsrc = &g_h[(size_t)(jb + hr) * HIDD + hq * 16];
#pragma unroll
            for (int k = 0; k < 4; k++) {
                float4 v = *(const float4*)(hsrc + k * 4);
                uint4 u = make_uint4(tf32_rna(v.x), tf32_rna(v.y),
                                     tf32_rna(v.z), tf32_rna(v.w));
                *(uint4*)&h_s[hr * HS_STRIDE + hq * 16 + k * 4] = u;
            }
        }

        // ---- w tile [128 i][64 j], tf32-rounded (denom uses identical bits) ----
        {
            const float* sdp = &g_sdst[jb + jh * 32];
#pragma unroll
            for (int q = 0; q < 8; q++) {
                float4 sd = *(const float4*)(sdp + q * 4);
                float ev[4] = {ssrc + sd.x, ssrc + sd.y, ssrc + sd.z, ssrc + sd.w};
                int am[4] = {av[q].x, av[q].y, av[q].z, av[q].w};
                uint4 wu;
                uint32_t* wp = &wu.x;
#pragma unroll
                for (int b = 0; b < 4; b++) {
                    float e = fmaxf(ev[b], ALPHA_S * ev[b]);   // leaky relu
                    float w = (am[b] > 0) ? __expf(e) : 0.f;
                    uint32_t wt = tf32_rna(w);
                    wp[b] = wt;
                    lp += __uint_as_float(wt);
                }
                *(uint4*)&w_s[i * WS_STRIDE + jh * 32 + q * 4] = wu;
            }
        }
        __syncthreads();

        // ---- mma: warp computes C[16 i][64 d] += w[16,64] x h[64,64] ----
        const int i0 = warp * 16;
#pragma unroll
        for (int kc = 0; kc < 8; kc++) {
            const int jc = kc * 8;
            uint32_t a[4];
            a[0] = w_s[(i0 + g) * WS_STRIDE + jc + c];
            a[1] = w_s[(i0 + 8 + g) * WS_STRIDE + jc + c];
            a[2] = w_s[(i0 + g) * WS_STRIDE + jc + c + 4];
            a[3] = w_s[(i0 + 8 + g) * WS_STRIDE + jc + c + 4];
#pragma unroll
            for (int nb = 0; nb < 8; nb++) {
                uint32_t b0 = h_s[(jc + c) * HS_STRIDE + nb * 8 + g];
                uint32_t b1 = h_s[(jc + c + 4) * HS_STRIDE + nb * 8 + g];
                mma_tf32(C[nb], a, b0, b1);
            }
        }
        __syncthreads();
    }

    // ---- epilogue: C regs -> g_acc ----
#pragma unroll
    for (int hrow = 0; hrow < 2; hrow++) {
        const int row = rb + warp * 16 + hrow * 8 + g;
        float* dst = &g_acc[split][(size_t)row * HIDD + c * 2];
#pragma unroll
        for (int nb = 0; nb < 8; nb++)
            *(float2*)(dst + nb * 8) =
                make_float2(C[nb][hrow * 2 + 0], C[nb][hrow * 2 + 1]);
    }

    // ---- denominators: combine jh halves (adjacent lanes) ----
    float o = __shfl_xor_sync(0xffffffffu, lp, 1);
    if (jh == 0) g_l[split][rb + i] = lp + o;
}

// ---------------- Kernel 3: out = relu( sum acc / sum l ), float4 ----------------
__global__ __launch_bounds__(256) void k_final(float* __restrict__ out) {
    int i4 = blockIdx.x * 256 + threadIdx.x;       // float4 index
    if (i4 >= NV * HIDD / 4) return;
    int row = i4 >> 4;
    float l = 0.f;
    float4 v = make_float4(0.f, 0.f, 0.f, 0.f);
#pragma unroll
    for (int s = 0; s < JSPLIT; s++) {
        l += g_l[s][row];
        float4 p = *(const float4*)&g_acc[s][(size_t)i4 * 4];
        v.x += p.x; v.y += p.y; v.z += p.z; v.w += p.w;
    }
    float inv = 1.f / l;
    v.x *= inv; v.y *= inv; v.z *= inv; v.w *= inv;
    v.x = v.x > 0.f ? v.x : 0.f;
    v.y = v.y > 0.f ? v.y : 0.f;
    v.z = v.z > 0.f ? v.z : 0.f;
    v.w = v.w > 0.f ? v.w : 0.f;
    *(float4*)&out[(size_t)i4 * 4] = v;
}

extern "C" void kernel_launch(void* const* d_in, const int* in_sizes, int n_in,
                              void* d_out, int out_size) {
    const float* X   = (const float*)d_in[0];
    const int*   adj = (const int*)  d_in[1];
    const float* W   = (const float*)d_in[3];
    const float* a   = (const float*)d_in[4];
    float* out = (float*)d_out;

    static int smem_set = 0;
    if (!smem_set) {
        cudaFuncSetAttribute(k_main, cudaFuncAttributeMaxDynamicSharedMemorySize,
                             SMEM_DYN);
        smem_set = 1;
    }

    k_gemm_h<<<NV / 64, 256>>>(X, W, a);
    k_main<<<dim3(NV / M_TILE, JSPLIT), 256, SMEM_DYN>>>(adj);
    k_final<<<NV * HIDD / 4 / 256, 256>>>(out);
}

// round 15
// speedup vs baseline: 1.3204x; 1.3204x over previous
#include <cuda_runtime.h>
#include <cuda_fp16.h>
#include <cstdint>

#define NV      8192
#define FEAT    256
#define HIDD    64
#define ALPHA_S 0.2f
#define JSPLIT  8
#define JCHUNK  (NV / JSPLIT)     // 1024
#define JTILE   32
#define M_TILE  128
#define NVH     (NV / 2)          // 4096 half2 per d-row

// ---------------- device scratch (no allocation allowed) ----------------
__device__ unsigned g_hp[HIDD * NVH];       // h as half2 pairs, [d][j/2], 1MB
__device__ float    g_ssrc[NV];
__device__ float    g_sdst[NV];
__device__ unsigned g_sdmax_u;              // monotone float key, max-idempotent
__device__ float    g_acc[JSPLIT][NV * HIDD];
__device__ float    g_l[JSPLIT][NV];

// ---------------- helpers ----------------
__device__ __forceinline__ unsigned fkey(float x) {
    unsigned u = __float_as_uint(x);
    return (u & 0x80000000u) ? ~u : (u | 0x80000000u);
}
__device__ __forceinline__ float funkey(unsigned k) {
    return (k & 0x80000000u) ? __uint_as_float(k ^ 0x80000000u)
                             : __uint_as_float(~k);
}

// m16n8k16 f16 HMMA, f32 accum (baseline PTX, sm_80+)
__device__ __forceinline__ void mma_f16(float* d, const unsigned* a,
                                        unsigned b0, unsigned b1) {
    asm volatile(
        "mma.sync.aligned.m16n8k16.row.col.f32.f16.f16.f32 "
        "{%0,%1,%2,%3}, {%4,%5,%6,%7}, {%8,%9}, {%0,%1,%2,%3};"
        : "+f"(d[0]), "+f"(d[1]), "+f"(d[2]), "+f"(d[3])
        : "r"(a[0]), "r"(a[1]), "r"(a[2]), "r"(a[3]), "r"(b0), "r"(b1));
}

// ---------------- Kernel 1: h = X @ W (fp32 exact), fused s + hp pack ----------------
// grid 512 x 16-row tiles (full chip), 256 threads: thread = (row r=t>>4, 4 cols q*4..)
__global__ __launch_bounds__(256) void k_gemm_h(const float* __restrict__ X,
                                                const float* __restrict__ W,
                                                const float* __restrict__ a) {
    __shared__ __align__(16) float Xs[16 * 260];
    __shared__ __align__(16) float Ws[64 * 64];
    const int t  = threadIdx.x;
    const int rb = blockIdx.x * 16;
    const int r  = t >> 4;
    const int q  = t & 15;

    // load X tile [16][256]
    {
        const float4* src = (const float4*)&X[(size_t)(rb + r) * FEAT + q * 16];
        float4* dst = (float4*)&Xs[r * 260 + q * 16];
#pragma unroll
        for (int k = 0; k < 4; k++) dst[k] = src[k];
    }

    float acc[4] = {0.f, 0.f, 0.f, 0.f};
    for (int kc = 0; kc < FEAT; kc += 64) {
        __syncthreads();   // drain Ws readers (also covers Xs on first pass)
        const float4* wsrc = (const float4*)(W + (size_t)kc * HIDD);
#pragma unroll
        for (int p = 0; p < 4; p++)
            ((float4*)Ws)[t + p * 256] = wsrc[t + p * 256];
        __syncthreads();
#pragma unroll 16
        for (int k = 0; k < 64; k++) {
            float x = Xs[r * 260 + kc + k];
            float4 w4 = *(const float4*)&Ws[k * 64 + q * 4];
            acc[0] = fmaf(x, w4.x, acc[0]);
            acc[1] = fmaf(x, w4.y, acc[1]);
            acc[2] = fmaf(x, w4.z, acc[2]);
            acc[3] = fmaf(x, w4.w, acc[3]);
        }
    }

    // pack h into half2 pairs: partner row = lane^16 (r^1), pair (even, odd)
#pragma unroll
    for (int c = 0; c < 4; c++) {
        float other = __shfl_xor_sync(0xffffffffu, acc[c], 16);
        if ((r & 1) == 0) {
            __half2 hv = __floats2half2_rn(acc[c], other);
            g_hp[(size_t)(q * 4 + c) * NVH + ((rb + r) >> 1)] =
                *reinterpret_cast<unsigned*>(&hv);
        }
    }

    // fused s_src/s_dst: reduce partial dots across the 16 q-lanes of this row
    float ps = 0.f, pd = 0.f;
#pragma unroll
    for (int c = 0; c < 4; c++) {
        ps = fmaf(acc[c], __ldg(&a[q * 4 + c]), ps);
        pd = fmaf(acc[c], __ldg(&a[64 + q * 4 + c]), pd);
    }
#pragma unroll
    for (int o = 1; o < 16; o <<= 1) {
        ps += __shfl_xor_sync(0xffffffffu, ps, o);
        pd += __shfl_xor_sync(0xffffffffu, pd, o);
    }
    if (q == 0) {
        g_ssrc[rb + r] = ps;
        g_sdst[rb + r] = pd;
        atomicMax(&g_sdmax_u, fkey(pd));   // idempotent across graph replays
    }
}

// ---------------- Kernel 2: fused w-phase + fp16 mma aggregation ----------------
// 128 thr / 4 warps, warp tile 32 i x 64 d (mb=2, nb=8), JTILE=32 (2 K16 chunks).
// w2_s stride 20 half2-words: A-frag banks 20g mod 32 = {0,4,...,28} + c -> conflict-free.
#define W2S 20
__global__ __launch_bounds__(128, 4) void k_main(const int* __restrict__ adj) {
    __shared__ __align__(16) unsigned w2_s[M_TILE * W2S];   // 10 KB

    const int t = threadIdx.x, lane = t & 31, warp = t >> 5;
    const int g = lane >> 2, c = lane & 3;
    const int rb = blockIdx.x * M_TILE;
    const int split = blockIdx.y;
    const int j0 = split * JCHUNK;

    const int ih = t >> 1;       // row pair base (rows ih and 64+ih)
    const int jh = t & 1;        // 16-j half
    const float sdmax = funkey(g_sdmax_u);
    const float ss0 = g_ssrc[rb + ih];
    const float ss1 = g_ssrc[rb + 64 + ih];
    const float x0 = ss0 + sdmax, x1 = ss1 + sdmax;
    const float M0 = fmaxf(x0, ALPHA_S * x0);   // leaky upper bound -> w <= 1
    const float M1 = fmaxf(x1, ALPHA_S * x1);

    const int* arow0 = adj + (size_t)(rb + ih) * NV + j0 + jh * 16;
    const int* arow1 = arow0 + (size_t)64 * NV;
    float lp0 = 0.f, lp1 = 0.f;

    float C[2][8][4] = {};

    // prefetch tile 0 adj (evict-first: single-use stream)
    int4 av[8];
#pragma unroll
    for (int q = 0; q < 4; q++) {
        av[q]     = __ldcs((const int4*)arow0 + q);
        av[4 + q] = __ldcs((const int4*)arow1 + q);
    }

    const int i0 = warp * 32;
    const unsigned jp0 = (unsigned)(j0 >> 1);

    for (int it = 0; it < JCHUNK / JTILE; ++it) {
        // ---- w-phase: w = exp(leaky(ss+sd) - Mi), fp16-rounded; lp uses same bits ----
        const float* sdp = &g_sdst[j0 + it * JTILE + jh * 16];
#pragma unroll
        for (int half = 0; half < 2; half++) {
            const float Mi = half ? M1 : M0;
            const float ss = half ? ss1 : ss0;
            float lpl = 0.f;
            unsigned wrow[8];
#pragma unroll
            for (int q = 0; q < 4; q++) {
                int4 A = av[half * 4 + q];
                float4 sd = *(const float4*)(sdp + q * 4);
                int   am[4] = {A.x, A.y, A.z, A.w};
                float ev[4] = {ss + sd.x, ss + sd.y, ss + sd.z, ss + sd.w};
                float w[4];
#pragma unroll
                for (int b = 0; b < 4; b++) {
                    float e = fmaxf(ev[b], ALPHA_S * ev[b]) - Mi;   // <= 0
                    w[b] = (am[b] > 0) ? __expf(e) : 0.f;
                }
                __half2 p0 = __floats2half2_rn(w[0], w[1]);
                __half2 p1 = __floats2half2_rn(w[2], w[3]);
                float2 f0 = __half22float2(p0);
                float2 f1 = __half22float2(p1);
                lpl += (f0.x + f0.y) + (f1.x + f1.y);
                wrow[q * 2]     = *reinterpret_cast<unsigned*>(&p0);
                wrow[q * 2 + 1] = *reinterpret_cast<unsigned*>(&p1);
            }
            unsigned* dst = &w2_s[(half * 64 + ih) * W2S + jh * 8];
            *(uint4*)dst       = make_uint4(wrow[0], wrow[1], wrow[2], wrow[3]);
            *(uint4*)(dst + 4) = make_uint4(wrow[4], wrow[5], wrow[6], wrow[7]);
            if (half) lp1 += lpl; else lp0 += lpl;
        }
        __syncthreads();

        // ---- prefetch next tile's adj during MMA ----
        if (it + 1 < JCHUNK / JTILE) {
            const int* a0n = arow0 + (it + 1) * JTILE;
            const int* a1n = arow1 + (it + 1) * JTILE;
#pragma unroll
            for (int q = 0; q < 4; q++) {
                av[q]     = __ldcs((const int4*)a0n + q);
                av[4 + q] = __ldcs((const int4*)a1n + q);
            }
        }

        // ---- MMA: C[32 i][64 d] += w[32 i,32 j] x h[32 j,64 d] ----
        const unsigned jpb = jp0 + it * (JTILE / 2);
#pragma unroll
        for (int kc = 0; kc < 2; kc++) {
            const int kp = kc * 8;
            unsigned a0[4], a1[4];
            a0[0] = w2_s[(i0 + g) * W2S + kp + c];
            a0[1] = w2_s[(i0 + 8 + g) * W2S + kp + c];
            a0[2] = w2_s[(i0 + g) * W2S + kp + c + 4];
            a0[3] = w2_s[(i0 + 8 + g) * W2S + kp + c + 4];
            a1[0] = w2_s[(i0 + 16 + g) * W2S + kp + c];
            a1[1] = w2_s[(i0 + 24 + g) * W2S + kp + c];
            a1[2] = w2_s[(i0 + 16 + g) * W2S + kp + c + 4];
            a1[3] = w2_s[(i0 + 24 + g) * W2S + kp + c + 4];
            const unsigned* hb = &g_hp[(size_t)g * NVH + jpb + kc * 8];
#pragma unroll
            for (int nb = 0; nb < 8; nb++) {
                unsigned b0 = __ldg(hb + (size_t)(nb * 8) * NVH + c);
                unsigned b1 = __ldg(hb + (size_t)(nb * 8) * NVH + c + 4);
                mma_f16(C[0][nb], a0, b0, b1);
                mma_f16(C[1][nb], a1, b0, b1);
            }
        }
        __syncthreads();
    }

    // ---- epilogue: C regs -> g_acc ----
#pragma unroll
    for (int mb = 0; mb < 2; mb++)
#pragma unroll
        for (int hrow = 0; hrow < 2; hrow++) {
            const int row = rb + warp * 32 + mb * 16 + hrow * 8 + g;
            float* dst = &g_acc[split][(size_t)row * HIDD + c * 2];
#pragma unroll
            for (int nb = 0; nb < 8; nb++)
                *(float2*)(dst + nb * 8) =
                    make_float2(C[mb][nb][hrow * 2 + 0], C[mb][nb][hrow * 2 + 1]);
        }

    // ---- denominators: combine jh halves (adjacent lanes) ----
    float o0 = __shfl_xor_sync(0xffffffffu, lp0, 1);
    float o1 = __shfl_xor_sync(0xffffffffu, lp1, 1);
    if (jh == 0) {
        g_l[split][rb + ih]      = lp0 + o0;
        g_l[split][rb + 64 + ih] = lp1 + o1;
    }
}

// ---------------- Kernel 3: out = relu( sum acc / sum l ), float4 ----------------
__global__ __launch_bounds__(256) void k_final(float* __restrict__ out) {
    int i4 = blockIdx.x * 256 + threadIdx.x;
    if (i4 >= NV * HIDD / 4) return;
    int row = i4 >> 4;
    float l = 0.f;
    float4 v = make_float4(0.f, 0.f, 0.f, 0.f);
#pragma unroll
    for (int s = 0; s < JSPLIT; s++) {
        l += g_l[s][row];
        float4 p = *(const float4*)&g_acc[s][(size_t)i4 * 4];
        v.x += p.x; v.y += p.y; v.z += p.z; v.w += p.w;
    }
    float inv = 1.f / l;
    v.x *= inv; v.y *= inv; v.z *= inv; v.w *= inv;
    v.x = v.x > 0.f ? v.x : 0.f;
    v.y = v.y > 0.f ? v.y : 0.f;
    v.z = v.z > 0.f ? v.z : 0.f;
    v.w = v.w > 0.f ? v.w : 0.f;
    *(float4*)&out[(size_t)i4 * 4] = v;
}

extern "C" void kernel_launch(void* const* d_in, const int* in_sizes, int n_in,
                              void* d_out, int out_size) {
    const float* X   = (const float*)d_in[0];
    const int*   adj = (const int*)  d_in[1];
    const float* W   = (const float*)d_in[3];
    const float* a   = (const float*)d_in[4];
    float* out = (float*)d_out;

    k_gemm_h<<<NV / 16, 256>>>(X, W, a);
    k_main<<<dim3(NV / M_TILE, JSPLIT), 128>>>(adj);
    k_final<<<NV * HIDD / 4 / 256, 256>>>(out);
}

// round 16
// speedup vs baseline: 1.9542x; 1.4800x over previous
#include <cuda_runtime.h>
#include <cuda_fp16.h>
#include <cstdint>

#define NV      8192
#define FEAT    256
#define HIDD    64
#define ALPHA_S 0.2f
#define JSPLIT  8
#define JCHUNK  (NV / JSPLIT)     // 1024
#define JTILE   32
#define M_TILE  128
#define NVH     (NV / 2)

// ---------------- device scratch (no allocation allowed) ----------------
__device__ unsigned g_hp[HIDD * NVH];       // h as half2 pairs [d][j/2], 1MB
__device__ float    g_ssrc[NV];
__device__ float    g_sdst[NV];
__device__ unsigned g_sdmax_u;              // monotone float key (max-idempotent)
__device__ float4   g_sd4[NV];              // (sd, Ed=e^{sd-max}, Fd=e^{.2(sd-max)}, 0)
__device__ float4   g_row4[NV];             // (-ss, A_i, B_i, 0)
__device__ float    g_acc[JSPLIT][NV * HIDD];
__device__ float    g_l[JSPLIT][NV];

// ---------------- helpers ----------------
__device__ __forceinline__ unsigned fkey(float x) {
    unsigned u = __float_as_uint(x);
    return (u & 0x80000000u) ? ~u : (u | 0x80000000u);
}
__device__ __forceinline__ float funkey(unsigned k) {
    return (k & 0x80000000u) ? __uint_as_float(k ^ 0x80000000u)
                             : __uint_as_float(~k);
}

// m16n8k16 f16 HMMA, f32 accum (baseline PTX, sm_80+)
__device__ __forceinline__ void mma_f16(float* d, const unsigned* a,
                                        unsigned b0, unsigned b1) {
    asm volatile(
        "mma.sync.aligned.m16n8k16.row.col.f32.f16.f16.f32 "
        "{%0,%1,%2,%3}, {%4,%5,%6,%7}, {%8,%9}, {%0,%1,%2,%3};"
        : "+f"(d[0]), "+f"(d[1]), "+f"(d[2]), "+f"(d[3])
        : "r"(a[0]), "r"(a[1]), "r"(a[2]), "r"(a[3]), "r"(b0), "r"(b1));
}

// ---------------- Kernel 1: h = X @ W (fp32), fused s + fp16 pack ----------------
// grid 256 x 32-row tiles, 128 threads: thread = 2 rows (rg*2, rg*2+1) x 8 cols.
__global__ __launch_bounds__(128) void k_gemm_h(const float* __restrict__ X,
                                                const float* __restrict__ W,
                                                const float* __restrict__ a) {
    __shared__ __align__(16) float Xs[32 * 68];
    __shared__ __align__(16) float Ws[64 * 64];
    const int t  = threadIdx.x, lane = t & 31;
    const int rb = blockIdx.x * 32;
    const int rg = t >> 3;          // 0..15
    const int q  = t & 7;           // 8-col group
    const int r0 = rg * 2, r1 = r0 + 1;

    float acc0[8] = {}, acc1[8] = {};

    for (int kc = 0; kc < FEAT; kc += 64) {
        __syncthreads();
        // X chunk [32][64]
#pragma unroll
        for (int p = 0; p < 4; p++) {
            int idx = p * 128 + t, row = idx >> 4, c4 = idx & 15;
            *(float4*)&Xs[row * 68 + c4 * 4] =
                *(const float4*)&X[(size_t)(rb + row) * FEAT + kc + c4 * 4];
        }
        // W chunk [64][64]
        {
            const float4* wsrc = (const float4*)(W + (size_t)kc * HIDD);
#pragma unroll
            for (int p = 0; p < 8; p++)
                ((float4*)Ws)[p * 128 + t] = wsrc[p * 128 + t];
        }
        __syncthreads();
#pragma unroll 16
        for (int k = 0; k < 64; k++) {
            float x0 = Xs[r0 * 68 + k];
            float x1 = Xs[r1 * 68 + k];
            float4 wa = *(const float4*)&Ws[k * 64 + q * 8];
            float4 wb = *(const float4*)&Ws[k * 64 + q * 8 + 4];
            acc0[0] = fmaf(x0, wa.x, acc0[0]); acc1[0] = fmaf(x1, wa.x, acc1[0]);
            acc0[1] = fmaf(x0, wa.y, acc0[1]); acc1[1] = fmaf(x1, wa.y, acc1[1]);
            acc0[2] = fmaf(x0, wa.z, acc0[2]); acc1[2] = fmaf(x1, wa.z, acc1[2]);
            acc0[3] = fmaf(x0, wa.w, acc0[3]); acc1[3] = fmaf(x1, wa.w, acc1[3]);
            acc0[4] = fmaf(x0, wb.x, acc0[4]); acc1[4] = fmaf(x1, wb.x, acc1[4]);
            acc0[5] = fmaf(x0, wb.y, acc0[5]); acc1[5] = fmaf(x1, wb.y, acc1[5]);
            acc0[6] = fmaf(x0, wb.z, acc0[6]); acc1[6] = fmaf(x1, wb.z, acc1[6]);
            acc0[7] = fmaf(x0, wb.w, acc0[7]); acc1[7] = fmaf(x1, wb.w, acc1[7]);
        }
    }

    // pack fp16 pairs (row r0, r1 are the j-pair) into g_hp[d][jpair]
    const int jp = (rb >> 1) + rg;
#pragma unroll
    for (int c = 0; c < 8; c++) {
        __half2 hv = __floats2half2_rn(acc0[c], acc1[c]);
        g_hp[(size_t)(q * 8 + c) * NVH + jp] = *reinterpret_cast<unsigned*>(&hv);
    }

    // fused s_src / s_dst for both rows
    float ps0 = 0.f, pd0 = 0.f, ps1 = 0.f, pd1 = 0.f;
#pragma unroll
    for (int c = 0; c < 8; c++) {
        float as = __ldg(&a[q * 8 + c]), ad = __ldg(&a[64 + q * 8 + c]);
        ps0 = fmaf(acc0[c], as, ps0); pd0 = fmaf(acc0[c], ad, pd0);
        ps1 = fmaf(acc1[c], as, ps1); pd1 = fmaf(acc1[c], ad, pd1);
    }
#pragma unroll
    for (int o = 1; o < 8; o <<= 1) {
        ps0 += __shfl_xor_sync(0xffffffffu, ps0, o);
        pd0 += __shfl_xor_sync(0xffffffffu, pd0, o);
        ps1 += __shfl_xor_sync(0xffffffffu, ps1, o);
        pd1 += __shfl_xor_sync(0xffffffffu, pd1, o);
    }
    if (q == 0) {
        g_ssrc[rb + r0] = ps0; g_sdst[rb + r0] = pd0;
        g_ssrc[rb + r1] = ps1; g_sdst[rb + r1] = pd1;
    }
    // one atomic per warp for global sdst max
    float m = fmaxf(pd0, pd1);
    m = fmaxf(m, __shfl_xor_sync(0xffffffffu, m, 8));
    m = fmaxf(m, __shfl_xor_sync(0xffffffffu, m, 16));
    if (lane == 0) atomicMax(&g_sdmax_u, fkey(m));
}

// ---------------- Kernel 2: per-row/col exp factor precompute ----------------
__global__ __launch_bounds__(256) void k_prep() {
    int i = blockIdx.x * 256 + threadIdx.x;
    const float sdmax = funkey(g_sdmax_u);
    float sd = g_sdst[i];
    g_sd4[i] = make_float4(sd, __expf(sd - sdmax),
                           __expf(ALPHA_S * (sd - sdmax)), 0.f);
    float ss = g_ssrc[i];
    float y = ss + sdmax;
    float M = fmaxf(y, ALPHA_S * y);                // leaky upper bound
    g_row4[i] = make_float4(-ss, __expf(y - M), __expf(ALPHA_S * y - M), 0.f);
}

// ---------------- Kernel 3: exp-free w-phase + fp16 mma (both operands smem) ----
// 128 thr / 4 warps, warp tile 32i x 64d, JTILE=32 (2 K16 chunks).
// w2_s / h2_s stride 20 words -> A/B fragment banks conflict-free.
#define W2S 20
__global__ __launch_bounds__(128, 4) void k_main(const int* __restrict__ adj) {
    __shared__ __align__(16) unsigned w2_s[M_TILE * W2S];   // 10 KB
    __shared__ __align__(16) unsigned h2_s[64 * W2S];       // 5 KB
    __shared__ __align__(16) float4 sd4_s[JTILE];           // 512 B

    const int t = threadIdx.x, lane = t & 31, warp = t >> 5;
    const int g = lane >> 2, c = lane & 3;
    const int rb = blockIdx.x * M_TILE;
    const int split = blockIdx.y;
    const int j0 = split * JCHUNK;

    const int ih = t >> 1;       // rows {ih, 64+ih}
    const int jh = t & 1;        // 16-j half
    float4 rw0 = g_row4[rb + ih];
    float4 rw1 = g_row4[rb + 64 + ih];
    const float th0 = rw0.x, Af0 = rw0.y, Bf0 = rw0.z;
    const float th1 = rw1.x, Af1 = rw1.y, Bf1 = rw1.z;

    const int* arow0 = adj + (size_t)(rb + ih) * NV + j0 + jh * 16;
    const int* arow1 = arow0 + (size_t)64 * NV;
    float lp0 = 0.f, lp1 = 0.f;
    float C[2][8][4] = {};

    // prefetch tile 0 adj (streaming)
    int4 av[8];
#pragma unroll
    for (int q = 0; q < 4; q++) {
        av[q]     = __ldcs((const int4*)arow0 + q);
        av[4 + q] = __ldcs((const int4*)arow1 + q);
    }

    const int i0 = warp * 32;
    const unsigned jp0 = (unsigned)(j0 >> 1);

    for (int it = 0; it < JCHUNK / JTILE; ++it) {
        const unsigned jpb = jp0 + it * (JTILE / 2);

        // ---- stage h2 tile [64 d][16 jpair] and sd4 tile ----
        {
            const int d = t >> 1, half8 = t & 1;
            const unsigned* src = &g_hp[(size_t)d * NVH + jpb + half8 * 8];
            unsigned* dst = &h2_s[d * W2S + half8 * 8];
            *(uint4*)dst       = *(const uint4*)src;
            *(uint4*)(dst + 4) = *(const uint4*)(src + 4);
            if (t < JTILE) sd4_s[t] = g_sd4[j0 + it * JTILE + t];
        }
        __syncthreads();

        // ---- w-phase: w = (sd>=th) ? A*Ed : B*Fd, adj-masked, fp16 bits ----
        {
            unsigned wr0[8], wr1[8];
            float l0 = 0.f, l1 = 0.f;
#pragma unroll
            for (int q = 0; q < 4; q++) {
                int am0[4] = {av[q].x, av[q].y, av[q].z, av[q].w};
                int am1[4] = {av[4 + q].x, av[4 + q].y, av[4 + q].z, av[4 + q].w};
                float w0[4], w1[4];
#pragma unroll
                for (int b = 0; b < 4; b++) {
                    float4 s4 = sd4_s[jh * 16 + q * 4 + b];
                    float u0 = (s4.x >= th0) ? Af0 * s4.y : Bf0 * s4.z;
                    float u1 = (s4.x >= th1) ? Af1 * s4.y : Bf1 * s4.z;
                    w0[b] = (am0[b] > 0) ? u0 : 0.f;
                    w1[b] = (am1[b] > 0) ? u1 : 0.f;
                }
                __half2 p00 = __floats2half2_rn(w0[0], w0[1]);
                __half2 p01 = __floats2half2_rn(w0[2], w0[3]);
                __half2 p10 = __floats2half2_rn(w1[0], w1[1]);
                __half2 p11 = __floats2half2_rn(w1[2], w1[3]);
                float2 f;
                f = __half22float2(p00); l0 += f.x + f.y;
                f = __half22float2(p01); l0 += f.x + f.y;
                f = __half22float2(p10); l1 += f.x + f.y;
                f = __half22float2(p11); l1 += f.x + f.y;
                wr0[q * 2] = *reinterpret_cast<unsigned*>(&p00);
                wr0[q * 2 + 1] = *reinterpret_cast<unsigned*>(&p01);
                wr1[q * 2] = *reinterpret_cast<unsigned*>(&p10);
                wr1[q * 2 + 1] = *reinterpret_cast<unsigned*>(&p11);
            }
            unsigned* d0 = &w2_s[ih * W2S + jh * 8];
            unsigned* d1 = &w2_s[(64 + ih) * W2S + jh * 8];
            *(uint4*)d0       = make_uint4(wr0[0], wr0[1], wr0[2], wr0[3]);
            *(uint4*)(d0 + 4) = make_uint4(wr0[4], wr0[5], wr0[6], wr0[7]);
            *(uint4*)d1       = make_uint4(wr1[0], wr1[1], wr1[2], wr1[3]);
            *(uint4*)(d1 + 4) = make_uint4(wr1[4], wr1[5], wr1[6], wr1[7]);
            lp0 += l0; lp1 += l1;
        }
        __syncthreads();

        // ---- prefetch next tile's adj during MMA ----
        if (it + 1 < JCHUNK / JTILE) {
            const int* a0n = arow0 + (it + 1) * JTILE;
            const int* a1n = arow1 + (it + 1) * JTILE;
#pragma unroll
            for (int q = 0; q < 4; q++) {
                av[q]     = __ldcs((const int4*)a0n + q);
                av[4 + q] = __ldcs((const int4*)a1n + q);
            }
        }

        // ---- MMA: C[32 i][64 d] += w[32,32j] x h[32j,64d] ----
#pragma unroll
        for (int kc = 0; kc < 2; kc++) {
            const int kp = kc * 8;
            unsigned a0[4], a1[4];
            a0[0] = w2_s[(i0 + g) * W2S + kp + c];
            a0[1] = w2_s[(i0 + 8 + g) * W2S + kp + c];
            a0[2] = w2_s[(i0 + g) * W2S + kp + c + 4];
            a0[3] = w2_s[(i0 + 8 + g) * W2S + kp + c + 4];
            a1[0] = w2_s[(i0 + 16 + g) * W2S + kp + c];
            a1[1] = w2_s[(i0 + 24 + g) * W2S + kp + c];
            a1[2] = w2_s[(i0 + 16 + g) * W2S + kp + c + 4];
            a1[3] = w2_s[(i0 + 24 + g) * W2S + kp + c + 4];
#pragma unroll
            for (int nb = 0; nb < 8; nb++) {
                unsigned b0 = h2_s[(nb * 8 + g) * W2S + kp + c];
                unsigned b1 = h2_s[(nb * 8 + g) * W2S + kp + c + 4];
                mma_f16(C[0][nb], a0, b0, b1);
                mma_f16(C[1][nb], a1, b0, b1);
            }
        }
        __syncthreads();   // protect h2_s/w2_s before next staging
    }

    // ---- epilogue ----
#pragma unroll
    for (int mb = 0; mb < 2; mb++)
#pragma unroll
        for (int hrow = 0; hrow < 2; hrow++) {
            const int row = rb + warp * 32 + mb * 16 + hrow * 8 + g;
            float* dst = &g_acc[split][(size_t)row * HIDD + c * 2];
#pragma unroll
            for (int nb = 0; nb < 8; nb++)
                *(float2*)(dst + nb * 8) =
                    make_float2(C[mb][nb][hrow * 2 + 0], C[mb][nb][hrow * 2 + 1]);
        }

    float o0 = __shfl_xor_sync(0xffffffffu, lp0, 1);
    float o1 = __shfl_xor_sync(0xffffffffu, lp1, 1);
    if (jh == 0) {
        g_l[split][rb + ih]      = lp0 + o0;
        g_l[split][rb + 64 + ih] = lp1 + o1;
    }
}

// ---------------- Kernel 4: out = relu( sum acc / sum l ) ----------------
__global__ __launch_bounds__(256) void k_final(float* __restrict__ out) {
    int i4 = blockIdx.x * 256 + threadIdx.x;
    if (i4 >= NV * HIDD / 4) return;
    int row = i4 >> 4;
    float l = 0.f;
    float4 v = make_float4(0.f, 0.f, 0.f, 0.f);
#pragma unroll
    for (int s = 0; s < JSPLIT; s++) {
        l += g_l[s][row];
        float4 p = *(const float4*)&g_acc[s][(size_t)i4 * 4];
        v.x += p.x; v.y += p.y; v.z += p.z; v.w += p.w;
    }
    float inv = 1.f / l;
    v.x *= inv; v.y *= inv; v.z *= inv; v.w *= inv;
    v.x = v.x > 0.f ? v.x : 0.f;
    v.y = v.y > 0.f ? v.y : 0.f;
    v.z = v.z > 0.f ? v.z : 0.f;
    v.w = v.w > 0.f ? v.w : 0.f;
    *(float4*)&out[(size_t)i4 * 4] = v;
}

extern "C" void kernel_launch(void* const* d_in, const int* in_sizes, int n_in,
                              void* d_out, int out_size) {
    const float* X   = (const float*)d_in[0];
    const int*   adj = (const int*)  d_in[1];
    const float* W   = (const float*)d_in[3];
    const float* a   = (const float*)d_in[4];
    float* out = (float*)d_out;

    k_gemm_h<<<NV / 32, 128>>>(X, W, a);
    k_prep<<<NV / 256, 256>>>();
    k_main<<<dim3(NV / M_TILE, JSPLIT), 128>>>(adj);
    k_final<<<NV * HIDD / 4 / 256, 256>>>(out);
}